// round 1
// baseline (speedup 1.0000x reference)
#include <cuda_runtime.h>
#include <cuda_bf16.h>
#include <cstdint>

#define N_NODES 100000
#define N_EDGES 1600000
#define D_IN    256
#define D_OUT   64
#define BN_EPS  1e-5f

// Scratch (device globals — no allocation allowed)
__device__ float g_y[(size_t)N_NODES * D_OUT];   // dinv[row] * (x W^T)
__device__ int   g_deg[N_NODES];
__device__ float g_dinv[N_NODES];

// ---------------------------------------------------------------------------
// Degree kernels
// ---------------------------------------------------------------------------
__global__ void k_deg_init() {
    int i = blockIdx.x * blockDim.x + threadIdx.x;
    if (i < N_NODES) g_deg[i] = 1;   // self-loop
}

__global__ void k_deg_count(const int* __restrict__ cols) {
    int e = blockIdx.x * blockDim.x + threadIdx.x;
    if (e < N_EDGES) atomicAdd(&g_deg[cols[e]], 1);
}

__global__ void k_dinv() {
    int i = blockIdx.x * blockDim.x + threadIdx.x;
    if (i < N_NODES) g_dinv[i] = rsqrtf((float)g_deg[i]);
}

// ---------------------------------------------------------------------------
// GEMM: y[n][d] = dinv[n] * sum_k x[n][k] * W[d][k]
// Block: 32 nodes x 64 douts, 128 threads, 4x4 register tile per thread.
// Also writes d_out = y (self-loop contribution of the aggregation).
// ---------------------------------------------------------------------------
__global__ __launch_bounds__(128) void k_gemm(const float* __restrict__ x,
                                              const float* __restrict__ W,
                                              float* __restrict__ out) {
    __shared__ float xs[32][68];   // 32 nodes x 64 k (+4 pad)
    __shared__ float ws[64][68];   // 64 douts x 64 k (+4 pad)

    const int tid = threadIdx.x;
    const int tx  = tid & 15;      // dout group: d0 = 4*tx
    const int ty  = tid >> 4;      // node group: n0 = 4*ty  (8 groups)
    const int nodeBase = blockIdx.x * 32;

    float acc[4][4] = {};

    for (int kc = 0; kc < D_IN; kc += 64) {
        // Load x tile: 32 x 64 floats = 512 float4, coalesced
        for (int idx = tid; idx < 32 * 16; idx += 128) {
            int n  = idx >> 4;
            int kq = (idx & 15) << 2;
            float4 v = *(const float4*)&x[(size_t)(nodeBase + n) * D_IN + kc + kq];
            *(float4*)&xs[n][kq] = v;
        }
        // Load W tile: 64 x 64 floats = 1024 float4
        for (int idx = tid; idx < 64 * 16; idx += 128) {
            int d  = idx >> 4;
            int kq = (idx & 15) << 2;
            float4 v = *(const float4*)&W[(size_t)d * D_IN + kc + kq];
            *(float4*)&ws[d][kq] = v;
        }
        __syncthreads();

        #pragma unroll
        for (int kk = 0; kk < 64; kk += 4) {
            float4 a[4], b[4];
            #pragma unroll
            for (int i = 0; i < 4; i++) a[i] = *(float4*)&xs[4 * ty + i][kk];
            #pragma unroll
            for (int j = 0; j < 4; j++) b[j] = *(float4*)&ws[4 * tx + j][kk];
            #pragma unroll
            for (int i = 0; i < 4; i++)
                #pragma unroll
                for (int j = 0; j < 4; j++) {
                    acc[i][j] += a[i].x * b[j].x;
                    acc[i][j] += a[i].y * b[j].y;
                    acc[i][j] += a[i].z * b[j].z;
                    acc[i][j] += a[i].w * b[j].w;
                }
        }
        __syncthreads();
    }

    const int n0 = nodeBase + 4 * ty;
    const int d0 = 4 * tx;
    #pragma unroll
    for (int i = 0; i < 4; i++) {
        float di = g_dinv[n0 + i];
        float4 v;
        v.x = acc[i][0] * di;
        v.y = acc[i][1] * di;
        v.z = acc[i][2] * di;
        v.w = acc[i][3] * di;
        *(float4*)&g_y[(size_t)(n0 + i) * D_OUT + d0] = v;
        *(float4*)&out[(size_t)(n0 + i) * D_OUT + d0] = v;   // self-loop seed
    }
}

// ---------------------------------------------------------------------------
// Scatter: out[col] += y[row] for every edge. 16 threads per edge, each a
// red.global.add.v4.f32 (no-return reduction, sm_90+).
// ---------------------------------------------------------------------------
__global__ __launch_bounds__(256) void k_scatter(const int* __restrict__ rows,
                                                 const int* __restrict__ cols,
                                                 float* __restrict__ out) {
    long long t = (long long)blockIdx.x * blockDim.x + threadIdx.x;
    if (t >= (long long)N_EDGES * 16) return;
    int e = (int)(t >> 4);
    int q = (int)(t & 15) << 2;
    int r = rows[e];
    int c = cols[e];
    float4 v = *(const float4*)&g_y[(size_t)r * D_OUT + q];
    float* p = &out[(size_t)c * D_OUT + q];
    asm volatile("red.global.add.v4.f32 [%0], {%1,%2,%3,%4};"
                 :: "l"(p), "f"(v.x), "f"(v.y), "f"(v.z), "f"(v.w)
                 : "memory");
}

// ---------------------------------------------------------------------------
// Epilogue: out = relu(((dinv[n]*agg) + bias - mean) * rsqrt(var+eps) * gamma + beta)
// ---------------------------------------------------------------------------
__global__ __launch_bounds__(256) void k_epi(const float* __restrict__ bias,
                                             const float* __restrict__ gamma,
                                             const float* __restrict__ beta,
                                             const float* __restrict__ mean,
                                             const float* __restrict__ var,
                                             float* __restrict__ out) {
    int t = blockIdx.x * blockDim.x + threadIdx.x;
    if (t >= N_NODES * 16) return;
    int n = t >> 4;
    int q = (t & 15) << 2;
    float di = g_dinv[n];
    float4 v = *(float4*)&out[(size_t)n * D_OUT + q];

    float r[4] = {v.x, v.y, v.z, v.w};
    #pragma unroll
    for (int j = 0; j < 4; j++) {
        int d = q + j;
        float s = rsqrtf(var[d] + BN_EPS);
        float o = (r[j] * di + bias[d] - mean[d]) * s * gamma[d] + beta[d];
        r[j] = fmaxf(o, 0.0f);
    }
    v.x = r[0]; v.y = r[1]; v.z = r[2]; v.w = r[3];
    *(float4*)&out[(size_t)n * D_OUT + q] = v;
}

// ---------------------------------------------------------------------------
extern "C" void kernel_launch(void* const* d_in, const int* in_sizes, int n_in,
                              void* d_out, int out_size) {
    const float* x     = (const float*)d_in[0];
    const int*   ei    = (const int*)  d_in[1];
    const float* W     = (const float*)d_in[2];
    const float* bias  = (const float*)d_in[3];
    const float* gamma = (const float*)d_in[4];
    const float* beta  = (const float*)d_in[5];
    const float* mean  = (const float*)d_in[6];
    const float* var   = (const float*)d_in[7];
    float* out = (float*)d_out;

    const int* rows = ei;            // edge_index[0] = source
    const int* cols = ei + N_EDGES;  // edge_index[1] = target

    k_deg_init <<<(N_NODES + 255) / 256, 256>>>();
    k_deg_count<<<(N_EDGES + 255) / 256, 256>>>(cols);
    k_dinv     <<<(N_NODES + 255) / 256, 256>>>();
    k_gemm     <<<N_NODES / 32, 128>>>(x, W, out);
    k_scatter  <<<(int)(((long long)N_EDGES * 16 + 255) / 256), 256>>>(rows, cols, out);
    k_epi      <<<(N_NODES * 16 + 255) / 256, 256>>>(bias, gamma, beta, mean, var, out);
}

// round 4
// speedup vs baseline: 1.7413x; 1.7413x over previous
#include <cuda_runtime.h>
#include <cuda_bf16.h>
#include <cstdint>

#define N_NODES 100000
#define N_EDGES 1600000
#define D_IN    256
#define D_OUT   64
#define BN_EPS  1e-5f

// Scratch (device globals — no allocation allowed)
__device__ float g_y[(size_t)N_NODES * D_OUT];   // dinv[row] * (x W^T)
__device__ int   g_deg[N_NODES];
__device__ float g_dinv[N_NODES];

// ---------------------------------------------------------------------------
// Degree kernels
// ---------------------------------------------------------------------------
__global__ void k_deg_init() {
    int i = blockIdx.x * blockDim.x + threadIdx.x;
    if (i < N_NODES) g_deg[i] = 1;   // self-loop
}
__global__ void k_deg_count(const int* __restrict__ cols) {
    int e = blockIdx.x * blockDim.x + threadIdx.x;
    if (e < N_EDGES) atomicAdd(&g_deg[cols[e]], 1);
}
__global__ void k_dinv() {
    int i = blockIdx.x * blockDim.x + threadIdx.x;
    if (i < N_NODES) g_dinv[i] = rsqrtf((float)g_deg[i]);
}

// ---------------------------------------------------------------------------
// Tensor-core GEMM via mma.sync (HMMA, baseline PTX — works on sm_103 target).
// y[n][d] = dinv[n] * sum_k x[n][k] * W[d][k], split-bf16:
//   x = xh + xl, W = wh + wl; acc += xh*wh + xh*wl + xl*wh  (fp32 accum)
// CTA: 128 nodes x 64 douts, 256 threads (8 warps, 16 rows/warp).
// K chunked by 64. smem rows padded to 72 bf16 (144B) for conflict-free frags.
// ---------------------------------------------------------------------------
#define ROWB 144                         // bytes per smem row (72 bf16)
static constexpr int SM_XHI = 0;
static constexpr int SM_XLO = SM_XHI + 128 * ROWB;   // 18432
static constexpr int SM_WHI = SM_XLO + 128 * ROWB;   // 36864
static constexpr int SM_WLO = SM_WHI + 64 * ROWB;    // 46080
static constexpr int SM_TOTAL = SM_WLO + 64 * ROWB;  // 55296

__device__ __forceinline__ void mma_bf16(float* c, const uint32_t* a,
                                         uint32_t b0, uint32_t b1) {
    asm volatile(
        "mma.sync.aligned.m16n8k16.row.col.f32.bf16.bf16.f32 "
        "{%0,%1,%2,%3}, {%4,%5,%6,%7}, {%8,%9}, {%0,%1,%2,%3};"
        : "+f"(c[0]), "+f"(c[1]), "+f"(c[2]), "+f"(c[3])
        : "r"(a[0]), "r"(a[1]), "r"(a[2]), "r"(a[3]), "r"(b0), "r"(b1));
}

__device__ __forceinline__ uint32_t lds_u32(const char* base, int off) {
    return *(const uint32_t*)(base + off);
}

__global__ __launch_bounds__(256) void k_gemm_mma(const float* __restrict__ x,
                                                  const float* __restrict__ Wp,
                                                  float* __restrict__ out) {
    extern __shared__ char sm[];
    const int tid = threadIdx.x;
    const int w   = tid >> 5;       // warp 0..7 -> rows [16w, 16w+16)
    const int lane = tid & 31;
    const int nodeBase = blockIdx.x * 128;

    float acc[8][4];
    #pragma unroll
    for (int nt = 0; nt < 8; nt++)
        #pragma unroll
        for (int j = 0; j < 4; j++) acc[nt][j] = 0.f;

    for (int c = 0; c < 4; c++) {
        const int kc = c * 64;

        // ---- load + split-convert x chunk: 128 rows x 64 floats ----
        for (int idx = tid; idx < 128 * 16; idx += 256) {
            int row = idx >> 4;
            int g   = idx & 15;            // float4 index; col = g*4
            int node = nodeBase + row;
            float4 v = make_float4(0.f, 0.f, 0.f, 0.f);
            if (node < N_NODES)
                v = *(const float4*)&x[(size_t)node * D_IN + kc + g * 4];
            float f[4] = {v.x, v.y, v.z, v.w};
            __nv_bfloat16 hi[4], lo[4];
            #pragma unroll
            for (int j = 0; j < 4; j++) {
                hi[j] = __float2bfloat16(f[j]);
                lo[j] = __float2bfloat16(f[j] - __bfloat162float(hi[j]));
            }
            int off = row * ROWB + g * 8;
            *(uint2*)(sm + SM_XHI + off) = *(uint2*)hi;
            *(uint2*)(sm + SM_XLO + off) = *(uint2*)lo;
        }
        // ---- load + split-convert W chunk: 64 rows x 64 floats ----
        for (int idx = tid; idx < 64 * 16; idx += 256) {
            int row = idx >> 4;
            int g   = idx & 15;
            float4 v = *(const float4*)&Wp[(size_t)row * D_IN + kc + g * 4];
            float f[4] = {v.x, v.y, v.z, v.w};
            __nv_bfloat16 hi[4], lo[4];
            #pragma unroll
            for (int j = 0; j < 4; j++) {
                hi[j] = __float2bfloat16(f[j]);
                lo[j] = __float2bfloat16(f[j] - __bfloat162float(hi[j]));
            }
            int off = row * ROWB + g * 8;
            *(uint2*)(sm + SM_WHI + off) = *(uint2*)hi;
            *(uint2*)(sm + SM_WLO + off) = *(uint2*)lo;
        }
        __syncthreads();

        // ---- MMA: 4 k16-steps, 8 n-tiles, 3 precision products ----
        #pragma unroll
        for (int ks = 0; ks < 4; ks++) {
            const int kb = ks * 32 + (lane & 3) * 4;   // byte offset of k pair
            const int ar = (w * 16 + (lane >> 2)) * ROWB;
            uint32_t ah[4], al[4];
            ah[0] = lds_u32(sm + SM_XHI, ar + kb);
            ah[1] = lds_u32(sm + SM_XHI, ar + 8 * ROWB + kb);
            ah[2] = lds_u32(sm + SM_XHI, ar + kb + 16);
            ah[3] = lds_u32(sm + SM_XHI, ar + 8 * ROWB + kb + 16);
            al[0] = lds_u32(sm + SM_XLO, ar + kb);
            al[1] = lds_u32(sm + SM_XLO, ar + 8 * ROWB + kb);
            al[2] = lds_u32(sm + SM_XLO, ar + kb + 16);
            al[3] = lds_u32(sm + SM_XLO, ar + 8 * ROWB + kb + 16);

            #pragma unroll
            for (int nt = 0; nt < 8; nt++) {
                const int br = (nt * 8 + (lane >> 2)) * ROWB;
                uint32_t bh0 = lds_u32(sm + SM_WHI, br + kb);
                uint32_t bh1 = lds_u32(sm + SM_WHI, br + kb + 16);
                uint32_t bl0 = lds_u32(sm + SM_WLO, br + kb);
                uint32_t bl1 = lds_u32(sm + SM_WLO, br + kb + 16);
                mma_bf16(acc[nt], ah, bh0, bh1);
                mma_bf16(acc[nt], ah, bl0, bl1);
                mma_bf16(acc[nt], al, bh0, bh1);
            }
        }
        __syncthreads();
    }

    // ---- store: scale by dinv[row], seed out = y (self-loop term) ----
    const int r0 = nodeBase + w * 16 + (lane >> 2);
    const int r1 = r0 + 8;
    const float di0 = (r0 < N_NODES) ? g_dinv[r0] : 0.f;
    const float di1 = (r1 < N_NODES) ? g_dinv[r1] : 0.f;
    #pragma unroll
    for (int nt = 0; nt < 8; nt++) {
        const int col = nt * 8 + (lane & 3) * 2;
        if (r0 < N_NODES) {
            float2 v = make_float2(acc[nt][0] * di0, acc[nt][1] * di0);
            *(float2*)&g_y[(size_t)r0 * D_OUT + col] = v;
            *(float2*)&out[(size_t)r0 * D_OUT + col] = v;
        }
        if (r1 < N_NODES) {
            float2 v = make_float2(acc[nt][2] * di1, acc[nt][3] * di1);
            *(float2*)&g_y[(size_t)r1 * D_OUT + col] = v;
            *(float2*)&out[(size_t)r1 * D_OUT + col] = v;
        }
    }
}

// ---------------------------------------------------------------------------
// Scatter: out[col] += y[row], 16 threads/edge, red.global.add.v4.f32
// ---------------------------------------------------------------------------
__global__ __launch_bounds__(256) void k_scatter(const int* __restrict__ rows,
                                                 const int* __restrict__ cols,
                                                 float* __restrict__ out) {
    long long t = (long long)blockIdx.x * blockDim.x + threadIdx.x;
    if (t >= (long long)N_EDGES * 16) return;
    int e = (int)(t >> 4);
    int q = (int)(t & 15) << 2;
    int r = rows[e];
    int c = cols[e];
    float4 v = *(const float4*)&g_y[(size_t)r * D_OUT + q];
    float* p = &out[(size_t)c * D_OUT + q];
    asm volatile("red.global.add.v4.f32 [%0], {%1,%2,%3,%4};"
                 :: "l"(p), "f"(v.x), "f"(v.y), "f"(v.z), "f"(v.w)
                 : "memory");
}

// ---------------------------------------------------------------------------
// Epilogue: out = relu(((agg*dinv) + bias - mean) * rsqrt(var+eps) * gamma + beta)
// ---------------------------------------------------------------------------
__global__ __launch_bounds__(256) void k_epi(const float* __restrict__ bias,
                                             const float* __restrict__ gamma,
                                             const float* __restrict__ beta,
                                             const float* __restrict__ mean,
                                             const float* __restrict__ var,
                                             float* __restrict__ out) {
    int t = blockIdx.x * blockDim.x + threadIdx.x;
    if (t >= N_NODES * 16) return;
    int n = t >> 4;
    int q = (t & 15) << 2;
    float di = g_dinv[n];
    float4 v = *(float4*)&out[(size_t)n * D_OUT + q];

    float r[4] = {v.x, v.y, v.z, v.w};
    #pragma unroll
    for (int j = 0; j < 4; j++) {
        int d = q + j;
        float s = rsqrtf(var[d] + BN_EPS);
        float o = (r[j] * di + bias[d] - mean[d]) * s * gamma[d] + beta[d];
        r[j] = fmaxf(o, 0.0f);
    }
    v.x = r[0]; v.y = r[1]; v.z = r[2]; v.w = r[3];
    *(float4*)&out[(size_t)n * D_OUT + q] = v;
}

// ---------------------------------------------------------------------------
extern "C" void kernel_launch(void* const* d_in, const int* in_sizes, int n_in,
                              void* d_out, int out_size) {
    const float* x     = (const float*)d_in[0];
    const int*   ei    = (const int*)  d_in[1];
    const float* W     = (const float*)d_in[2];
    const float* bias  = (const float*)d_in[3];
    const float* gamma = (const float*)d_in[4];
    const float* beta  = (const float*)d_in[5];
    const float* mean  = (const float*)d_in[6];
    const float* var   = (const float*)d_in[7];
    float* out = (float*)d_out;

    const int* rows = ei;            // edge_index[0] = source
    const int* cols = ei + N_EDGES;  // edge_index[1] = target

    cudaFuncSetAttribute(k_gemm_mma, cudaFuncAttributeMaxDynamicSharedMemorySize, SM_TOTAL);

    k_deg_init <<<(N_NODES + 255) / 256, 256>>>();
    k_deg_count<<<(N_EDGES + 255) / 256, 256>>>(cols);
    k_dinv     <<<(N_NODES + 255) / 256, 256>>>();
    k_gemm_mma <<<(N_NODES + 127) / 128, 256, SM_TOTAL>>>(x, W, out);
    k_scatter  <<<(int)(((long long)N_EDGES * 16 + 255) / 256), 256>>>(rows, cols, out);
    k_epi      <<<(N_NODES * 16 + 255) / 256, 256>>>(bias, gamma, beta, mean, var, out);
}

// round 5
// speedup vs baseline: 2.2059x; 1.2668x over previous
#include <cuda_runtime.h>
#include <cuda_bf16.h>
#include <cstdint>

#define N_NODES 100000
#define N_EDGES 1600000
#define D_IN    256
#define D_OUT   64
#define BN_EPS  1e-5f

#define SCAN_BS 1024
#define N_BLKS  ((N_NODES + SCAN_BS - 1) / SCAN_BS)   // 98

// Scratch (device globals — no allocation allowed)
__device__ float g_y[(size_t)N_NODES * D_OUT];   // dinv[row] * (x W^T)
__device__ int   g_deg[N_NODES];                 // edge-only in-degree
__device__ float g_dinv[N_NODES];
__device__ int   g_off[N_NODES + 1];             // CSR offsets (by target)
__device__ int   g_cur[N_NODES];                 // fill cursors
__device__ int   g_adj[N_EDGES];                 // source node per slot
__device__ int   g_part[N_BLKS];                 // scan partials
__device__ int   g_pscan[N_BLKS];

// ---------------------------------------------------------------------------
// Degree + CSR build
// ---------------------------------------------------------------------------
__global__ void k_zero() {
    int i = blockIdx.x * blockDim.x + threadIdx.x;
    if (i < N_NODES) g_deg[i] = 0;
}
__global__ void k_count(const int* __restrict__ cols) {
    int e = blockIdx.x * blockDim.x + threadIdx.x;
    if (e < N_EDGES) atomicAdd(&g_deg[cols[e]], 1);
}
// per-block exclusive scan (1024 elems), block total -> g_part
__global__ __launch_bounds__(SCAN_BS) void k_scan1() {
    __shared__ int sh[SCAN_BS];
    int tid = threadIdx.x;
    int i = blockIdx.x * SCAN_BS + tid;
    int v = (i < N_NODES) ? g_deg[i] : 0;
    sh[tid] = v;
    __syncthreads();
    #pragma unroll
    for (int d = 1; d < SCAN_BS; d <<= 1) {
        int t = (tid >= d) ? sh[tid - d] : 0;
        __syncthreads();
        sh[tid] += t;
        __syncthreads();
    }
    if (i < N_NODES) g_off[i] = sh[tid] - v;          // exclusive within block
    if (tid == SCAN_BS - 1) g_part[blockIdx.x] = sh[tid];
}
// scan of the 98 block partials (single block)
__global__ __launch_bounds__(128) void k_scan2() {
    __shared__ int sh[128];
    int tid = threadIdx.x;
    int v = (tid < N_BLKS) ? g_part[tid] : 0;
    sh[tid] = v;
    __syncthreads();
    #pragma unroll
    for (int d = 1; d < 128; d <<= 1) {
        int t = (tid >= d) ? sh[tid - d] : 0;
        __syncthreads();
        sh[tid] += t;
        __syncthreads();
    }
    if (tid < N_BLKS) g_pscan[tid] = sh[tid] - v;     // exclusive
}
// finalize offsets + cursors + dinv
__global__ void k_scan3() {
    int i = blockIdx.x * blockDim.x + threadIdx.x;
    if (i < N_NODES) {
        int o = g_off[i] + g_pscan[i >> 10];
        g_off[i] = o;
        g_cur[i] = o;
        g_dinv[i] = rsqrtf((float)(g_deg[i] + 1));    // +1 self-loop
    }
    if (i == 0) g_off[N_NODES] = N_EDGES;
}
__global__ void k_fill(const int* __restrict__ rows, const int* __restrict__ cols) {
    int e = blockIdx.x * blockDim.x + threadIdx.x;
    if (e < N_EDGES) {
        int pos = atomicAdd(&g_cur[cols[e]], 1);
        g_adj[pos] = rows[e];
    }
}

// ---------------------------------------------------------------------------
// Tensor-core GEMM via mma.sync (HMMA). y = dinv * (x W^T), split-bf16.
// CTA: 128 nodes x 64 douts, 256 threads. K chunked by 64.
// ---------------------------------------------------------------------------
#define ROWB 144
static constexpr int SM_XHI = 0;
static constexpr int SM_XLO = SM_XHI + 128 * ROWB;
static constexpr int SM_WHI = SM_XLO + 128 * ROWB;
static constexpr int SM_WLO = SM_WHI + 64 * ROWB;
static constexpr int SM_TOTAL = SM_WLO + 64 * ROWB;  // 55296

__device__ __forceinline__ void mma_bf16(float* c, const uint32_t* a,
                                         uint32_t b0, uint32_t b1) {
    asm volatile(
        "mma.sync.aligned.m16n8k16.row.col.f32.bf16.bf16.f32 "
        "{%0,%1,%2,%3}, {%4,%5,%6,%7}, {%8,%9}, {%0,%1,%2,%3};"
        : "+f"(c[0]), "+f"(c[1]), "+f"(c[2]), "+f"(c[3])
        : "r"(a[0]), "r"(a[1]), "r"(a[2]), "r"(a[3]), "r"(b0), "r"(b1));
}
__device__ __forceinline__ uint32_t lds_u32(const char* base, int off) {
    return *(const uint32_t*)(base + off);
}

__global__ __launch_bounds__(256) void k_gemm_mma(const float* __restrict__ x,
                                                  const float* __restrict__ Wp) {
    extern __shared__ char sm[];
    const int tid = threadIdx.x;
    const int w   = tid >> 5;
    const int lane = tid & 31;
    const int nodeBase = blockIdx.x * 128;

    float acc[8][4];
    #pragma unroll
    for (int nt = 0; nt < 8; nt++)
        #pragma unroll
        for (int j = 0; j < 4; j++) acc[nt][j] = 0.f;

    for (int c = 0; c < 4; c++) {
        const int kc = c * 64;
        for (int idx = tid; idx < 128 * 16; idx += 256) {
            int row = idx >> 4;
            int g   = idx & 15;
            int node = nodeBase + row;
            float4 v = make_float4(0.f, 0.f, 0.f, 0.f);
            if (node < N_NODES)
                v = *(const float4*)&x[(size_t)node * D_IN + kc + g * 4];
            float f[4] = {v.x, v.y, v.z, v.w};
            __nv_bfloat16 hi[4], lo[4];
            #pragma unroll
            for (int j = 0; j < 4; j++) {
                hi[j] = __float2bfloat16(f[j]);
                lo[j] = __float2bfloat16(f[j] - __bfloat162float(hi[j]));
            }
            int off = row * ROWB + g * 8;
            *(uint2*)(sm + SM_XHI + off) = *(uint2*)hi;
            *(uint2*)(sm + SM_XLO + off) = *(uint2*)lo;
        }
        for (int idx = tid; idx < 64 * 16; idx += 256) {
            int row = idx >> 4;
            int g   = idx & 15;
            float4 v = *(const float4*)&Wp[(size_t)row * D_IN + kc + g * 4];
            float f[4] = {v.x, v.y, v.z, v.w};
            __nv_bfloat16 hi[4], lo[4];
            #pragma unroll
            for (int j = 0; j < 4; j++) {
                hi[j] = __float2bfloat16(f[j]);
                lo[j] = __float2bfloat16(f[j] - __bfloat162float(hi[j]));
            }
            int off = row * ROWB + g * 8;
            *(uint2*)(sm + SM_WHI + off) = *(uint2*)hi;
            *(uint2*)(sm + SM_WLO + off) = *(uint2*)lo;
        }
        __syncthreads();

        #pragma unroll
        for (int ks = 0; ks < 4; ks++) {
            const int kb = ks * 32 + (lane & 3) * 4;
            const int ar = (w * 16 + (lane >> 2)) * ROWB;
            uint32_t ah[4], al[4];
            ah[0] = lds_u32(sm + SM_XHI, ar + kb);
            ah[1] = lds_u32(sm + SM_XHI, ar + 8 * ROWB + kb);
            ah[2] = lds_u32(sm + SM_XHI, ar + kb + 16);
            ah[3] = lds_u32(sm + SM_XHI, ar + 8 * ROWB + kb + 16);
            al[0] = lds_u32(sm + SM_XLO, ar + kb);
            al[1] = lds_u32(sm + SM_XLO, ar + 8 * ROWB + kb);
            al[2] = lds_u32(sm + SM_XLO, ar + kb + 16);
            al[3] = lds_u32(sm + SM_XLO, ar + 8 * ROWB + kb + 16);

            #pragma unroll
            for (int nt = 0; nt < 8; nt++) {
                const int br = (nt * 8 + (lane >> 2)) * ROWB;
                uint32_t bh0 = lds_u32(sm + SM_WHI, br + kb);
                uint32_t bh1 = lds_u32(sm + SM_WHI, br + kb + 16);
                uint32_t bl0 = lds_u32(sm + SM_WLO, br + kb);
                uint32_t bl1 = lds_u32(sm + SM_WLO, br + kb + 16);
                mma_bf16(acc[nt], ah, bh0, bh1);
                mma_bf16(acc[nt], ah, bl0, bl1);
                mma_bf16(acc[nt], al, bh0, bh1);
            }
        }
        __syncthreads();
    }

    const int r0 = nodeBase + w * 16 + (lane >> 2);
    const int r1 = r0 + 8;
    const float di0 = (r0 < N_NODES) ? g_dinv[r0] : 0.f;
    const float di1 = (r1 < N_NODES) ? g_dinv[r1] : 0.f;
    #pragma unroll
    for (int nt = 0; nt < 8; nt++) {
        const int col = nt * 8 + (lane & 3) * 2;
        if (r0 < N_NODES)
            *(float2*)&g_y[(size_t)r0 * D_OUT + col] =
                make_float2(acc[nt][0] * di0, acc[nt][1] * di0);
        if (r1 < N_NODES)
            *(float2*)&g_y[(size_t)r1 * D_OUT + col] =
                make_float2(acc[nt][2] * di1, acc[nt][3] * di1);
    }
}

// ---------------------------------------------------------------------------
// Gather: one warp per node. acc = y[node] + sum_{r in adj[node]} y[r];
// fused epilogue: relu((acc*dinv + bias - mean)*rsqrt(var+eps)*gamma + beta)
// ---------------------------------------------------------------------------
__global__ __launch_bounds__(256) void k_gather(const float* __restrict__ bias,
                                                const float* __restrict__ gamma,
                                                const float* __restrict__ beta,
                                                const float* __restrict__ mean,
                                                const float* __restrict__ var,
                                                float* __restrict__ out) {
    const int warp = (blockIdx.x * blockDim.x + threadIdx.x) >> 5;
    const int lane = threadIdx.x & 31;
    if (warp >= N_NODES) return;
    const int node = warp;
    const int c0 = lane * 2;

    const int s = g_off[node];
    const int e = g_off[node + 1];

    float2 acc = *(const float2*)&g_y[(size_t)node * D_OUT + c0];  // self-loop

    for (int base = s; base < e; base += 32) {
        int r = 0;
        if (base + lane < e) r = g_adj[base + lane];
        const int cnt = min(32, e - base);
        int j = 0;
        for (; j + 4 <= cnt; j += 4) {
            int r0 = __shfl_sync(0xffffffffu, r, j);
            int r1 = __shfl_sync(0xffffffffu, r, j + 1);
            int r2 = __shfl_sync(0xffffffffu, r, j + 2);
            int r3 = __shfl_sync(0xffffffffu, r, j + 3);
            float2 v0 = *(const float2*)&g_y[(size_t)r0 * D_OUT + c0];
            float2 v1 = *(const float2*)&g_y[(size_t)r1 * D_OUT + c0];
            float2 v2 = *(const float2*)&g_y[(size_t)r2 * D_OUT + c0];
            float2 v3 = *(const float2*)&g_y[(size_t)r3 * D_OUT + c0];
            acc.x += v0.x + v1.x + v2.x + v3.x;
            acc.y += v0.y + v1.y + v2.y + v3.y;
        }
        for (; j < cnt; j++) {
            int rr = __shfl_sync(0xffffffffu, r, j);
            float2 v = *(const float2*)&g_y[(size_t)rr * D_OUT + c0];
            acc.x += v.x;
            acc.y += v.y;
        }
    }

    const float di = g_dinv[node];
    float sc0 = rsqrtf(var[c0] + BN_EPS) * gamma[c0];
    float sc1 = rsqrtf(var[c0 + 1] + BN_EPS) * gamma[c0 + 1];
    float2 o;
    o.x = fmaxf((acc.x * di + bias[c0]     - mean[c0])     * sc0 + beta[c0],     0.f);
    o.y = fmaxf((acc.y * di + bias[c0 + 1] - mean[c0 + 1]) * sc1 + beta[c0 + 1], 0.f);
    *(float2*)&out[(size_t)node * D_OUT + c0] = o;
}

// ---------------------------------------------------------------------------
extern "C" void kernel_launch(void* const* d_in, const int* in_sizes, int n_in,
                              void* d_out, int out_size) {
    const float* x     = (const float*)d_in[0];
    const int*   ei    = (const int*)  d_in[1];
    const float* W     = (const float*)d_in[2];
    const float* bias  = (const float*)d_in[3];
    const float* gamma = (const float*)d_in[4];
    const float* beta  = (const float*)d_in[5];
    const float* mean  = (const float*)d_in[6];
    const float* var   = (const float*)d_in[7];
    float* out = (float*)d_out;

    const int* rows = ei;            // edge_index[0] = source
    const int* cols = ei + N_EDGES;  // edge_index[1] = target

    cudaFuncSetAttribute(k_gemm_mma, cudaFuncAttributeMaxDynamicSharedMemorySize, SM_TOTAL);

    k_zero  <<<(N_NODES + 255) / 256, 256>>>();
    k_count <<<(N_EDGES + 255) / 256, 256>>>(cols);
    k_scan1 <<<N_BLKS, SCAN_BS>>>();
    k_scan2 <<<1, 128>>>();
    k_scan3 <<<(N_NODES + 255) / 256, 256>>>();
    k_fill  <<<(N_EDGES + 255) / 256, 256>>>(rows, cols);
    k_gemm_mma<<<(N_NODES + 127) / 128, 256, SM_TOTAL>>>(x, W);
    k_gather<<<(N_NODES * 32 + 255) / 256, 256>>>(bias, gamma, beta, mean, var, out);
}

// round 6
// speedup vs baseline: 2.6309x; 1.1927x over previous
#include <cuda_runtime.h>
#include <cuda_bf16.h>
#include <cstdint>

#define N_NODES 100000
#define N_EDGES 1600000
#define D_IN    256
#define D_OUT   64
#define BN_EPS  1e-5f

#define SCAN_BS 1024
#define N_BLKS  ((N_NODES + SCAN_BS - 1) / SCAN_BS)   // 98

// Scratch (device globals — no allocation allowed)
__device__ float g_y[(size_t)N_NODES * D_OUT];   // dinv[row] * (x W^T)
__device__ int   g_deg[N_NODES];                 // edge-only in-degree
__device__ float g_dinv[N_NODES];
__device__ int   g_off[N_NODES + 1];             // CSR offsets (by target)
__device__ int   g_cur[N_NODES];                 // fill cursors
__device__ int   g_adj[N_EDGES];                 // source node per slot
__device__ int   g_part[N_BLKS];                 // scan partials
__device__ int   g_pscan[N_BLKS];

// ---------------------------------------------------------------------------
// Degree + CSR build
// ---------------------------------------------------------------------------
__global__ void k_zero() {
    int i = blockIdx.x * blockDim.x + threadIdx.x;
    if (i < N_NODES) g_deg[i] = 0;
}
__global__ void k_count(const int* __restrict__ cols) {
    int e = blockIdx.x * blockDim.x + threadIdx.x;
    if (e < N_EDGES) atomicAdd(&g_deg[cols[e]], 1);
}
__global__ __launch_bounds__(SCAN_BS) void k_scan1() {
    __shared__ int sh[SCAN_BS];
    int tid = threadIdx.x;
    int i = blockIdx.x * SCAN_BS + tid;
    int v = (i < N_NODES) ? g_deg[i] : 0;
    sh[tid] = v;
    __syncthreads();
    #pragma unroll
    for (int d = 1; d < SCAN_BS; d <<= 1) {
        int t = (tid >= d) ? sh[tid - d] : 0;
        __syncthreads();
        sh[tid] += t;
        __syncthreads();
    }
    if (i < N_NODES) g_off[i] = sh[tid] - v;
    if (tid == SCAN_BS - 1) g_part[blockIdx.x] = sh[tid];
}
__global__ __launch_bounds__(128) void k_scan2() {
    __shared__ int sh[128];
    int tid = threadIdx.x;
    int v = (tid < N_BLKS) ? g_part[tid] : 0;
    sh[tid] = v;
    __syncthreads();
    #pragma unroll
    for (int d = 1; d < 128; d <<= 1) {
        int t = (tid >= d) ? sh[tid - d] : 0;
        __syncthreads();
        sh[tid] += t;
        __syncthreads();
    }
    if (tid < N_BLKS) g_pscan[tid] = sh[tid] - v;
}
__global__ void k_scan3() {
    int i = blockIdx.x * blockDim.x + threadIdx.x;
    if (i < N_NODES) {
        int o = g_off[i] + g_pscan[i >> 10];
        g_off[i] = o;
        g_cur[i] = o;
        g_dinv[i] = rsqrtf((float)(g_deg[i] + 1));    // +1 self-loop
    }
    if (i == 0) g_off[N_NODES] = N_EDGES;
}
__global__ void k_fill(const int* __restrict__ rows, const int* __restrict__ cols) {
    int e = blockIdx.x * blockDim.x + threadIdx.x;
    if (e < N_EDGES) {
        int pos = atomicAdd(&g_cur[cols[e]], 1);
        g_adj[pos] = rows[e];
    }
}

// ---------------------------------------------------------------------------
// Tensor-core GEMM via mma.sync, software-pipelined:
// while chunk c's MMAs run, chunk c+1's LDGs are already in flight (register
// staging). y = dinv * (x W^T), split-bf16 (hi*hi + hi*lo + lo*hi).
// CTA: 128 nodes x 64 douts, 256 threads. K chunked by 64.
// ---------------------------------------------------------------------------
#define ROWB 144
static constexpr int SM_XHI = 0;
static constexpr int SM_XLO = SM_XHI + 128 * ROWB;
static constexpr int SM_WHI = SM_XLO + 128 * ROWB;
static constexpr int SM_WLO = SM_WHI + 64 * ROWB;
static constexpr int SM_TOTAL = SM_WLO + 64 * ROWB;  // 55296

__device__ __forceinline__ void mma_bf16(float* c, const uint32_t* a,
                                         uint32_t b0, uint32_t b1) {
    asm volatile(
        "mma.sync.aligned.m16n8k16.row.col.f32.bf16.bf16.f32 "
        "{%0,%1,%2,%3}, {%4,%5,%6,%7}, {%8,%9}, {%0,%1,%2,%3};"
        : "+f"(c[0]), "+f"(c[1]), "+f"(c[2]), "+f"(c[3])
        : "r"(a[0]), "r"(a[1]), "r"(a[2]), "r"(a[3]), "r"(b0), "r"(b1));
}
__device__ __forceinline__ uint32_t lds_u32(const char* base, int off) {
    return *(const uint32_t*)(base + off);
}

__device__ __forceinline__ void load_chunk_regs(const float* __restrict__ x,
                                                const float* __restrict__ Wp,
                                                int nodeBase, int kc, int tid,
                                                float4* xv, float4* wv) {
    #pragma unroll
    for (int i = 0; i < 8; i++) {
        int idx = tid + 256 * i;
        int row = idx >> 4, g = idx & 15;
        int node = nodeBase + row;
        xv[i] = (node < N_NODES)
              ? *(const float4*)&x[(size_t)node * D_IN + kc + g * 4]
              : make_float4(0.f, 0.f, 0.f, 0.f);
    }
    #pragma unroll
    for (int i = 0; i < 4; i++) {
        int idx = tid + 256 * i;
        int row = idx >> 4, g = idx & 15;
        wv[i] = *(const float4*)&Wp[(size_t)row * D_IN + kc + g * 4];
    }
}

__device__ __forceinline__ void store_chunk_smem(char* sm, int tid,
                                                 const float4* xv, const float4* wv) {
    #pragma unroll
    for (int i = 0; i < 8; i++) {
        int idx = tid + 256 * i;
        int row = idx >> 4, g = idx & 15;
        float f[4] = {xv[i].x, xv[i].y, xv[i].z, xv[i].w};
        __nv_bfloat16 hi[4], lo[4];
        #pragma unroll
        for (int j = 0; j < 4; j++) {
            hi[j] = __float2bfloat16(f[j]);
            lo[j] = __float2bfloat16(f[j] - __bfloat162float(hi[j]));
        }
        int off = row * ROWB + g * 8;
        *(uint2*)(sm + SM_XHI + off) = *(uint2*)hi;
        *(uint2*)(sm + SM_XLO + off) = *(uint2*)lo;
    }
    #pragma unroll
    for (int i = 0; i < 4; i++) {
        int idx = tid + 256 * i;
        int row = idx >> 4, g = idx & 15;
        float f[4] = {wv[i].x, wv[i].y, wv[i].z, wv[i].w};
        __nv_bfloat16 hi[4], lo[4];
        #pragma unroll
        for (int j = 0; j < 4; j++) {
            hi[j] = __float2bfloat16(f[j]);
            lo[j] = __float2bfloat16(f[j] - __bfloat162float(hi[j]));
        }
        int off = row * ROWB + g * 8;
        *(uint2*)(sm + SM_WHI + off) = *(uint2*)hi;
        *(uint2*)(sm + SM_WLO + off) = *(uint2*)lo;
    }
}

__global__ __launch_bounds__(256) void k_gemm_mma(const float* __restrict__ x,
                                                  const float* __restrict__ Wp) {
    extern __shared__ char sm[];
    const int tid = threadIdx.x;
    const int w   = tid >> 5;
    const int lane = tid & 31;
    const int nodeBase = blockIdx.x * 128;

    float acc[8][4];
    #pragma unroll
    for (int nt = 0; nt < 8; nt++)
        #pragma unroll
        for (int j = 0; j < 4; j++) acc[nt][j] = 0.f;

    float4 xv[8], wv[4];

    // prologue: chunk 0 into smem
    load_chunk_regs(x, Wp, nodeBase, 0, tid, xv, wv);
    store_chunk_smem(sm, tid, xv, wv);
    __syncthreads();

    for (int c = 0; c < 4; c++) {
        // prefetch next chunk while this chunk's MMAs run
        if (c < 3) load_chunk_regs(x, Wp, nodeBase, (c + 1) * 64, tid, xv, wv);

        #pragma unroll
        for (int ks = 0; ks < 4; ks++) {
            const int kb = ks * 32 + (lane & 3) * 4;
            const int ar = (w * 16 + (lane >> 2)) * ROWB;
            uint32_t ah[4], al[4];
            ah[0] = lds_u32(sm + SM_XHI, ar + kb);
            ah[1] = lds_u32(sm + SM_XHI, ar + 8 * ROWB + kb);
            ah[2] = lds_u32(sm + SM_XHI, ar + kb + 16);
            ah[3] = lds_u32(sm + SM_XHI, ar + 8 * ROWB + kb + 16);
            al[0] = lds_u32(sm + SM_XLO, ar + kb);
            al[1] = lds_u32(sm + SM_XLO, ar + 8 * ROWB + kb);
            al[2] = lds_u32(sm + SM_XLO, ar + kb + 16);
            al[3] = lds_u32(sm + SM_XLO, ar + 8 * ROWB + kb + 16);

            #pragma unroll
            for (int nt = 0; nt < 8; nt++) {
                const int br = (nt * 8 + (lane >> 2)) * ROWB;
                uint32_t bh0 = lds_u32(sm + SM_WHI, br + kb);
                uint32_t bh1 = lds_u32(sm + SM_WHI, br + kb + 16);
                uint32_t bl0 = lds_u32(sm + SM_WLO, br + kb);
                uint32_t bl1 = lds_u32(sm + SM_WLO, br + kb + 16);
                mma_bf16(acc[nt], ah, bh0, bh1);
                mma_bf16(acc[nt], ah, bl0, bl1);
                mma_bf16(acc[nt], al, bh0, bh1);
            }
        }
        __syncthreads();
        if (c < 3) {
            store_chunk_smem(sm, tid, xv, wv);
            __syncthreads();
        }
    }

    const int r0 = nodeBase + w * 16 + (lane >> 2);
    const int r1 = r0 + 8;
    const float di0 = (r0 < N_NODES) ? g_dinv[r0] : 0.f;
    const float di1 = (r1 < N_NODES) ? g_dinv[r1] : 0.f;
    #pragma unroll
    for (int nt = 0; nt < 8; nt++) {
        const int col = nt * 8 + (lane & 3) * 2;
        if (r0 < N_NODES)
            *(float2*)&g_y[(size_t)r0 * D_OUT + col] =
                make_float2(acc[nt][0] * di0, acc[nt][1] * di0);
        if (r1 < N_NODES)
            *(float2*)&g_y[(size_t)r1 * D_OUT + col] =
                make_float2(acc[nt][2] * di1, acc[nt][3] * di1);
    }
}

// ---------------------------------------------------------------------------
// Gather: one warp per node. acc = y[node] + sum_{r in adj[node]} y[r];
// fused epilogue: relu((acc*dinv + bias - mean)*rsqrt(var+eps)*gamma + beta)
// ---------------------------------------------------------------------------
__global__ __launch_bounds__(256) void k_gather(const float* __restrict__ bias,
                                                const float* __restrict__ gamma,
                                                const float* __restrict__ beta,
                                                const float* __restrict__ mean,
                                                const float* __restrict__ var,
                                                float* __restrict__ out) {
    const int warp = (blockIdx.x * blockDim.x + threadIdx.x) >> 5;
    const int lane = threadIdx.x & 31;
    if (warp >= N_NODES) return;
    const int node = warp;
    const int c0 = lane * 2;

    const int s = g_off[node];
    const int e = g_off[node + 1];

    float2 acc = *(const float2*)&g_y[(size_t)node * D_OUT + c0];  // self-loop

    for (int base = s; base < e; base += 32) {
        int r = 0;
        if (base + lane < e) r = g_adj[base + lane];
        const int cnt = min(32, e - base);
        int j = 0;
        for (; j + 4 <= cnt; j += 4) {
            int r0 = __shfl_sync(0xffffffffu, r, j);
            int r1 = __shfl_sync(0xffffffffu, r, j + 1);
            int r2 = __shfl_sync(0xffffffffu, r, j + 2);
            int r3 = __shfl_sync(0xffffffffu, r, j + 3);
            float2 v0 = *(const float2*)&g_y[(size_t)r0 * D_OUT + c0];
            float2 v1 = *(const float2*)&g_y[(size_t)r1 * D_OUT + c0];
            float2 v2 = *(const float2*)&g_y[(size_t)r2 * D_OUT + c0];
            float2 v3 = *(const float2*)&g_y[(size_t)r3 * D_OUT + c0];
            acc.x += v0.x + v1.x + v2.x + v3.x;
            acc.y += v0.y + v1.y + v2.y + v3.y;
        }
        for (; j < cnt; j++) {
            int rr = __shfl_sync(0xffffffffu, r, j);
            float2 v = *(const float2*)&g_y[(size_t)rr * D_OUT + c0];
            acc.x += v.x;
            acc.y += v.y;
        }
    }

    const float di = g_dinv[node];
    float sc0 = rsqrtf(var[c0] + BN_EPS) * gamma[c0];
    float sc1 = rsqrtf(var[c0 + 1] + BN_EPS) * gamma[c0 + 1];
    float2 o;
    o.x = fmaxf((acc.x * di + bias[c0]     - mean[c0])     * sc0 + beta[c0],     0.f);
    o.y = fmaxf((acc.y * di + bias[c0 + 1] - mean[c0 + 1]) * sc1 + beta[c0 + 1], 0.f);
    *(float2*)&out[(size_t)node * D_OUT + c0] = o;
}

// ---------------------------------------------------------------------------
extern "C" void kernel_launch(void* const* d_in, const int* in_sizes, int n_in,
                              void* d_out, int out_size) {
    const float* x     = (const float*)d_in[0];
    const int*   ei    = (const int*)  d_in[1];
    const float* W     = (const float*)d_in[2];
    const float* bias  = (const float*)d_in[3];
    const float* gamma = (const float*)d_in[4];
    const float* beta  = (const float*)d_in[5];
    const float* mean  = (const float*)d_in[6];
    const float* var   = (const float*)d_in[7];
    float* out = (float*)d_out;

    const int* rows = ei;            // edge_index[0] = source
    const int* cols = ei + N_EDGES;  // edge_index[1] = target

    cudaFuncSetAttribute(k_gemm_mma, cudaFuncAttributeMaxDynamicSharedMemorySize, SM_TOTAL);

    k_zero  <<<(N_NODES + 255) / 256, 256>>>();
    k_count <<<(N_EDGES + 255) / 256, 256>>>(cols);
    k_scan1 <<<N_BLKS, SCAN_BS>>>();
    k_scan2 <<<1, 128>>>();
    k_scan3 <<<(N_NODES + 255) / 256, 256>>>();
    k_fill  <<<(N_EDGES + 255) / 256, 256>>>(rows, cols);
    k_gemm_mma<<<(N_NODES + 127) / 128, 256, SM_TOTAL>>>(x, W);
    k_gather<<<(N_NODES * 32 + 255) / 256, 256>>>(bias, gamma, beta, mean, var, out);
}

// round 7
// speedup vs baseline: 2.9191x; 1.1095x over previous
#include <cuda_runtime.h>
#include <cuda_bf16.h>
#include <cstdint>

#define N_NODES 100000
#define N_EDGES 1600000
#define D_IN    256
#define D_OUT   64
#define BN_EPS  1e-5f

// Scratch (device globals — no allocation allowed)
__device__ float g_y[(size_t)N_NODES * D_OUT];   // x W^T (UNscaled)
__device__ int   g_deg[N_NODES];                 // edge-only in-degree
__device__ float g_dinv[N_NODES];
__device__ int   g_off[N_NODES];                 // CSR offsets (by target)
__device__ int   g_cur[N_NODES];                 // fill cursors
__device__ int   g_adj[N_EDGES];                 // source node per slot
__device__ int   g_total;                        // global offset cursor

// ---------------------------------------------------------------------------
// CSR build branch (independent of GEMM)
// ---------------------------------------------------------------------------
__global__ void k_zero() {
    int i = blockIdx.x * blockDim.x + threadIdx.x;
    if (i < N_NODES) g_deg[i] = 0;
    if (i == 0) g_total = 0;
}
__global__ void k_count(const int* __restrict__ cols) {
    int e = blockIdx.x * blockDim.x + threadIdx.x;
    if (e < N_EDGES) atomicAdd(&g_deg[cols[e]], 1);
}
// single-kernel offsets: block shuffle-scan + atomicAdd block base.
// (offset assignment order is nondeterministic across blocks but any valid
//  partition of [0,N_EDGES) is correct — gather walks s..s+deg per node)
__global__ __launch_bounds__(256) void k_offsets() {
    __shared__ int wt[8];
    __shared__ int bbase;
    const int tid = threadIdx.x;
    const int lane = tid & 31, wid = tid >> 5;
    const int i = blockIdx.x * 256 + tid;
    const int d = (i < N_NODES) ? g_deg[i] : 0;

    int v = d;  // inclusive warp scan
    #pragma unroll
    for (int o = 1; o < 32; o <<= 1) {
        int t = __shfl_up_sync(0xffffffffu, v, o);
        if (lane >= o) v += t;
    }
    if (lane == 31) wt[wid] = v;
    __syncthreads();
    if (tid == 0) {
        int s = 0;
        #pragma unroll
        for (int w = 0; w < 8; w++) { int t = wt[w]; wt[w] = s; s += t; }
        bbase = atomicAdd(&g_total, s);
    }
    __syncthreads();
    if (i < N_NODES) {
        int o = bbase + wt[wid] + v - d;   // exclusive prefix
        g_off[i] = o;
        g_cur[i] = o;
        g_dinv[i] = rsqrtf((float)(d + 1));   // +1 self-loop
    }
}
__global__ void k_fill(const int* __restrict__ rows, const int* __restrict__ cols) {
    int e = blockIdx.x * blockDim.x + threadIdx.x;
    if (e < N_EDGES) {
        int pos = atomicAdd(&g_cur[cols[e]], 1);
        g_adj[pos] = rows[e];
    }
}

// ---------------------------------------------------------------------------
// Tensor-core GEMM via mma.sync, software-pipelined. y = x W^T (unscaled),
// split-bf16 (hi*hi + hi*lo + lo*hi). CTA: 128 nodes x 64 douts, 256 thr.
// ---------------------------------------------------------------------------
#define ROWB 144
static constexpr int SM_XHI = 0;
static constexpr int SM_XLO = SM_XHI + 128 * ROWB;
static constexpr int SM_WHI = SM_XLO + 128 * ROWB;
static constexpr int SM_WLO = SM_WHI + 64 * ROWB;
static constexpr int SM_TOTAL = SM_WLO + 64 * ROWB;  // 55296

__device__ __forceinline__ void mma_bf16(float* c, const uint32_t* a,
                                         uint32_t b0, uint32_t b1) {
    asm volatile(
        "mma.sync.aligned.m16n8k16.row.col.f32.bf16.bf16.f32 "
        "{%0,%1,%2,%3}, {%4,%5,%6,%7}, {%8,%9}, {%0,%1,%2,%3};"
        : "+f"(c[0]), "+f"(c[1]), "+f"(c[2]), "+f"(c[3])
        : "r"(a[0]), "r"(a[1]), "r"(a[2]), "r"(a[3]), "r"(b0), "r"(b1));
}
__device__ __forceinline__ uint32_t lds_u32(const char* base, int off) {
    return *(const uint32_t*)(base + off);
}

__device__ __forceinline__ void load_chunk_regs(const float* __restrict__ x,
                                                const float* __restrict__ Wp,
                                                int nodeBase, int kc, int tid,
                                                float4* xv, float4* wv) {
    #pragma unroll
    for (int i = 0; i < 8; i++) {
        int idx = tid + 256 * i;
        int row = idx >> 4, g = idx & 15;
        int node = nodeBase + row;
        xv[i] = (node < N_NODES)
              ? *(const float4*)&x[(size_t)node * D_IN + kc + g * 4]
              : make_float4(0.f, 0.f, 0.f, 0.f);
    }
    #pragma unroll
    for (int i = 0; i < 4; i++) {
        int idx = tid + 256 * i;
        int row = idx >> 4, g = idx & 15;
        wv[i] = *(const float4*)&Wp[(size_t)row * D_IN + kc + g * 4];
    }
}

__device__ __forceinline__ void store_chunk_smem(char* sm, int tid,
                                                 const float4* xv, const float4* wv) {
    #pragma unroll
    for (int i = 0; i < 8; i++) {
        int idx = tid + 256 * i;
        int row = idx >> 4, g = idx & 15;
        float f[4] = {xv[i].x, xv[i].y, xv[i].z, xv[i].w};
        __nv_bfloat16 hi[4], lo[4];
        #pragma unroll
        for (int j = 0; j < 4; j++) {
            hi[j] = __float2bfloat16(f[j]);
            lo[j] = __float2bfloat16(f[j] - __bfloat162float(hi[j]));
        }
        int off = row * ROWB + g * 8;
        *(uint2*)(sm + SM_XHI + off) = *(uint2*)hi;
        *(uint2*)(sm + SM_XLO + off) = *(uint2*)lo;
    }
    #pragma unroll
    for (int i = 0; i < 4; i++) {
        int idx = tid + 256 * i;
        int row = idx >> 4, g = idx & 15;
        float f[4] = {wv[i].x, wv[i].y, wv[i].z, wv[i].w};
        __nv_bfloat16 hi[4], lo[4];
        #pragma unroll
        for (int j = 0; j < 4; j++) {
            hi[j] = __float2bfloat16(f[j]);
            lo[j] = __float2bfloat16(f[j] - __bfloat162float(hi[j]));
        }
        int off = row * ROWB + g * 8;
        *(uint2*)(sm + SM_WHI + off) = *(uint2*)hi;
        *(uint2*)(sm + SM_WLO + off) = *(uint2*)lo;
    }
}

__global__ __launch_bounds__(256) void k_gemm_mma(const float* __restrict__ x,
                                                  const float* __restrict__ Wp) {
    extern __shared__ char sm[];
    const int tid = threadIdx.x;
    const int w   = tid >> 5;
    const int lane = tid & 31;
    const int nodeBase = blockIdx.x * 128;

    float acc[8][4];
    #pragma unroll
    for (int nt = 0; nt < 8; nt++)
        #pragma unroll
        for (int j = 0; j < 4; j++) acc[nt][j] = 0.f;

    float4 xv[8], wv[4];
    load_chunk_regs(x, Wp, nodeBase, 0, tid, xv, wv);
    store_chunk_smem(sm, tid, xv, wv);
    __syncthreads();

    for (int c = 0; c < 4; c++) {
        if (c < 3) load_chunk_regs(x, Wp, nodeBase, (c + 1) * 64, tid, xv, wv);

        #pragma unroll
        for (int ks = 0; ks < 4; ks++) {
            const int kb = ks * 32 + (lane & 3) * 4;
            const int ar = (w * 16 + (lane >> 2)) * ROWB;
            uint32_t ah[4], al[4];
            ah[0] = lds_u32(sm + SM_XHI, ar + kb);
            ah[1] = lds_u32(sm + SM_XHI, ar + 8 * ROWB + kb);
            ah[2] = lds_u32(sm + SM_XHI, ar + kb + 16);
            ah[3] = lds_u32(sm + SM_XHI, ar + 8 * ROWB + kb + 16);
            al[0] = lds_u32(sm + SM_XLO, ar + kb);
            al[1] = lds_u32(sm + SM_XLO, ar + 8 * ROWB + kb);
            al[2] = lds_u32(sm + SM_XLO, ar + kb + 16);
            al[3] = lds_u32(sm + SM_XLO, ar + 8 * ROWB + kb + 16);

            #pragma unroll
            for (int nt = 0; nt < 8; nt++) {
                const int br = (nt * 8 + (lane >> 2)) * ROWB;
                uint32_t bh0 = lds_u32(sm + SM_WHI, br + kb);
                uint32_t bh1 = lds_u32(sm + SM_WHI, br + kb + 16);
                uint32_t bl0 = lds_u32(sm + SM_WLO, br + kb);
                uint32_t bl1 = lds_u32(sm + SM_WLO, br + kb + 16);
                mma_bf16(acc[nt], ah, bh0, bh1);
                mma_bf16(acc[nt], ah, bl0, bl1);
                mma_bf16(acc[nt], al, bh0, bh1);
            }
        }
        __syncthreads();
        if (c < 3) {
            store_chunk_smem(sm, tid, xv, wv);
            __syncthreads();
        }
    }

    const int r0 = nodeBase + w * 16 + (lane >> 2);
    const int r1 = r0 + 8;
    #pragma unroll
    for (int nt = 0; nt < 8; nt++) {
        const int col = nt * 8 + (lane & 3) * 2;
        if (r0 < N_NODES)
            *(float2*)&g_y[(size_t)r0 * D_OUT + col] = make_float2(acc[nt][0], acc[nt][1]);
        if (r1 < N_NODES)
            *(float2*)&g_y[(size_t)r1 * D_OUT + col] = make_float2(acc[nt][2], acc[nt][3]);
    }
}

// ---------------------------------------------------------------------------
// Gather: one warp per node. acc = dinv[n]*y[n] + sum_r dinv[r]*y[r];
// fused epilogue: relu((acc*dinv[n] + bias - mean)*rsqrt(var+eps)*gamma + beta)
// ---------------------------------------------------------------------------
__global__ __launch_bounds__(256) void k_gather(const float* __restrict__ bias,
                                                const float* __restrict__ gamma,
                                                const float* __restrict__ beta,
                                                const float* __restrict__ mean,
                                                const float* __restrict__ var,
                                                float* __restrict__ out) {
    const int warp = (blockIdx.x * blockDim.x + threadIdx.x) >> 5;
    const int lane = threadIdx.x & 31;
    if (warp >= N_NODES) return;
    const int node = warp;
    const int c0 = lane * 2;

    const int s = g_off[node];
    const int e = s + g_deg[node];
    const float di = g_dinv[node];

    float2 yv = *(const float2*)&g_y[(size_t)node * D_OUT + c0];
    float2 acc = make_float2(yv.x * di, yv.y * di);   // self-loop (× di again later)

    for (int base = s; base < e; base += 32) {
        int r = 0;
        float dr = 0.f;
        if (base + lane < e) {
            r = g_adj[base + lane];
            dr = g_dinv[r];
        }
        const int cnt = min(32, e - base);
        int j = 0;
        for (; j + 4 <= cnt; j += 4) {
            int r0 = __shfl_sync(0xffffffffu, r, j);
            int r1 = __shfl_sync(0xffffffffu, r, j + 1);
            int r2 = __shfl_sync(0xffffffffu, r, j + 2);
            int r3 = __shfl_sync(0xffffffffu, r, j + 3);
            float d0 = __shfl_sync(0xffffffffu, dr, j);
            float d1 = __shfl_sync(0xffffffffu, dr, j + 1);
            float d2 = __shfl_sync(0xffffffffu, dr, j + 2);
            float d3 = __shfl_sync(0xffffffffu, dr, j + 3);
            float2 v0 = *(const float2*)&g_y[(size_t)r0 * D_OUT + c0];
            float2 v1 = *(const float2*)&g_y[(size_t)r1 * D_OUT + c0];
            float2 v2 = *(const float2*)&g_y[(size_t)r2 * D_OUT + c0];
            float2 v3 = *(const float2*)&g_y[(size_t)r3 * D_OUT + c0];
            acc.x += d0 * v0.x + d1 * v1.x + d2 * v2.x + d3 * v3.x;
            acc.y += d0 * v0.y + d1 * v1.y + d2 * v2.y + d3 * v3.y;
        }
        for (; j < cnt; j++) {
            int rr = __shfl_sync(0xffffffffu, r, j);
            float dd = __shfl_sync(0xffffffffu, dr, j);
            float2 v = *(const float2*)&g_y[(size_t)rr * D_OUT + c0];
            acc.x += dd * v.x;
            acc.y += dd * v.y;
        }
    }

    float sc0 = rsqrtf(var[c0] + BN_EPS) * gamma[c0];
    float sc1 = rsqrtf(var[c0 + 1] + BN_EPS) * gamma[c0 + 1];
    float2 o;
    o.x = fmaxf((acc.x * di + bias[c0]     - mean[c0])     * sc0 + beta[c0],     0.f);
    o.y = fmaxf((acc.y * di + bias[c0 + 1] - mean[c0 + 1]) * sc1 + beta[c0 + 1], 0.f);
    *(float2*)&out[(size_t)node * D_OUT + c0] = o;
}

// ---------------------------------------------------------------------------
extern "C" void kernel_launch(void* const* d_in, const int* in_sizes, int n_in,
                              void* d_out, int out_size) {
    const float* x     = (const float*)d_in[0];
    const int*   ei    = (const int*)  d_in[1];
    const float* W     = (const float*)d_in[2];
    const float* bias  = (const float*)d_in[3];
    const float* gamma = (const float*)d_in[4];
    const float* beta  = (const float*)d_in[5];
    const float* mean  = (const float*)d_in[6];
    const float* var   = (const float*)d_in[7];
    float* out = (float*)d_out;

    const int* rows = ei;            // edge_index[0] = source
    const int* cols = ei + N_EDGES;  // edge_index[1] = target

    static cudaStream_t s2 = nullptr;
    static cudaEvent_t evFork = nullptr, evJoin = nullptr;
    if (!s2) {
        cudaStreamCreateWithFlags(&s2, cudaStreamNonBlocking);
        cudaEventCreateWithFlags(&evFork, cudaEventDisableTiming);
        cudaEventCreateWithFlags(&evJoin, cudaEventDisableTiming);
        cudaFuncSetAttribute(k_gemm_mma, cudaFuncAttributeMaxDynamicSharedMemorySize, SM_TOTAL);
    }

    // fork: CSR build on s2, GEMM on the capture (default) stream
    cudaEventRecord(evFork, 0);
    cudaStreamWaitEvent(s2, evFork, 0);

    k_zero   <<<(N_NODES + 255) / 256, 256, 0, s2>>>();
    k_count  <<<(N_EDGES + 255) / 256, 256, 0, s2>>>(cols);
    k_offsets<<<(N_NODES + 255) / 256, 256, 0, s2>>>();
    k_fill   <<<(N_EDGES + 255) / 256, 256, 0, s2>>>(rows, cols);

    k_gemm_mma<<<(N_NODES + 127) / 128, 256, SM_TOTAL>>>(x, W);

    // join
    cudaEventRecord(evJoin, s2);
    cudaStreamWaitEvent(0, evJoin, 0);

    k_gather<<<(N_NODES * 32 + 255) / 256, 256>>>(bias, gamma, beta, mean, var, out);
}

// round 9
// speedup vs baseline: 2.9313x; 1.0042x over previous
#include <cuda_runtime.h>
#include <cuda_bf16.h>
#include <cuda_fp16.h>
#include <cstdint>

#define N_NODES 100000
#define N_EDGES 1600000
#define D_IN    256
#define D_OUT   64
#define BN_EPS  1e-5f

// Scratch (device globals — no allocation allowed)
__device__ __half2 g_yh[(size_t)N_NODES * 32];   // x W^T as half2 (32 pairs = 64 cols)
__device__ int   g_deg[N_NODES];                 // edge-only in-degree
__device__ float g_dinv[N_NODES];
__device__ int   g_off[N_NODES];                 // CSR offsets (by target)
__device__ int   g_cur[N_NODES];                 // fill cursors
__device__ int   g_adj[N_EDGES];                 // source node per slot
__device__ int   g_total;                        // global offset cursor

// ---------------------------------------------------------------------------
// CSR build branch (independent of GEMM)
// ---------------------------------------------------------------------------
__global__ void k_zero() {
    int i = blockIdx.x * blockDim.x + threadIdx.x;
    if (i < N_NODES) g_deg[i] = 0;
    if (i == 0) g_total = 0;
}
__global__ void k_count(const int* __restrict__ cols) {
    int e = blockIdx.x * blockDim.x + threadIdx.x;
    if (e < N_EDGES) atomicAdd(&g_deg[cols[e]], 1);
}
// single-kernel offsets: block shuffle-scan + atomicAdd block base.
__global__ __launch_bounds__(256) void k_offsets() {
    __shared__ int wt[8];
    __shared__ int bbase;
    const int tid = threadIdx.x;
    const int lane = tid & 31, wid = tid >> 5;
    const int i = blockIdx.x * 256 + tid;
    const int d = (i < N_NODES) ? g_deg[i] : 0;

    int v = d;
    #pragma unroll
    for (int o = 1; o < 32; o <<= 1) {
        int t = __shfl_up_sync(0xffffffffu, v, o);
        if (lane >= o) v += t;
    }
    if (lane == 31) wt[wid] = v;
    __syncthreads();
    if (tid == 0) {
        int s = 0;
        #pragma unroll
        for (int w = 0; w < 8; w++) { int t = wt[w]; wt[w] = s; s += t; }
        bbase = atomicAdd(&g_total, s);
    }
    __syncthreads();
    if (i < N_NODES) {
        int o = bbase + wt[wid] + v - d;
        g_off[i] = o;
        g_cur[i] = o;
        g_dinv[i] = rsqrtf((float)(d + 1));   // +1 self-loop
    }
}
__global__ void k_fill(const int* __restrict__ rows, const int* __restrict__ cols) {
    int e = blockIdx.x * blockDim.x + threadIdx.x;
    if (e < N_EDGES) {
        int pos = atomicAdd(&g_cur[cols[e]], 1);
        g_adj[pos] = rows[e];
    }
}

// ---------------------------------------------------------------------------
// Tensor-core GEMM via mma.sync, software-pipelined. y = x W^T (unscaled),
// split-bf16 (hi*hi + hi*lo + lo*hi), fp32 accum, half2 store.
// CTA: 128 nodes x 64 douts, 256 threads.
// ---------------------------------------------------------------------------
#define ROWB 144
static constexpr int SM_XHI = 0;
static constexpr int SM_XLO = SM_XHI + 128 * ROWB;
static constexpr int SM_WHI = SM_XLO + 128 * ROWB;
static constexpr int SM_WLO = SM_WHI + 64 * ROWB;
static constexpr int SM_TOTAL = SM_WLO + 64 * ROWB;  // 55296

__device__ __forceinline__ void mma_bf16(float* c, const uint32_t* a,
                                         uint32_t b0, uint32_t b1) {
    asm volatile(
        "mma.sync.aligned.m16n8k16.row.col.f32.bf16.bf16.f32 "
        "{%0,%1,%2,%3}, {%4,%5,%6,%7}, {%8,%9}, {%0,%1,%2,%3};"
        : "+f"(c[0]), "+f"(c[1]), "+f"(c[2]), "+f"(c[3])
        : "r"(a[0]), "r"(a[1]), "r"(a[2]), "r"(a[3]), "r"(b0), "r"(b1));
}
__device__ __forceinline__ uint32_t lds_u32(const char* base, int off) {
    return *(const uint32_t*)(base + off);
}

__device__ __forceinline__ void load_chunk_regs(const float* __restrict__ x,
                                                const float* __restrict__ Wp,
                                                int nodeBase, int kc, int tid,
                                                float4* xv, float4* wv) {
    #pragma unroll
    for (int i = 0; i < 8; i++) {
        int idx = tid + 256 * i;
        int row = idx >> 4, g = idx & 15;
        int node = nodeBase + row;
        xv[i] = (node < N_NODES)
              ? *(const float4*)&x[(size_t)node * D_IN + kc + g * 4]
              : make_float4(0.f, 0.f, 0.f, 0.f);
    }
    #pragma unroll
    for (int i = 0; i < 4; i++) {
        int idx = tid + 256 * i;
        int row = idx >> 4, g = idx & 15;
        wv[i] = *(const float4*)&Wp[(size_t)row * D_IN + kc + g * 4];
    }
}

__device__ __forceinline__ void store_chunk_smem(char* sm, int tid,
                                                 const float4* xv, const float4* wv) {
    #pragma unroll
    for (int i = 0; i < 8; i++) {
        int idx = tid + 256 * i;
        int row = idx >> 4, g = idx & 15;
        float f[4] = {xv[i].x, xv[i].y, xv[i].z, xv[i].w};
        __nv_bfloat16 hi[4], lo[4];
        #pragma unroll
        for (int j = 0; j < 4; j++) {
            hi[j] = __float2bfloat16(f[j]);
            lo[j] = __float2bfloat16(f[j] - __bfloat162float(hi[j]));
        }
        int off = row * ROWB + g * 8;
        *(uint2*)(sm + SM_XHI + off) = *(uint2*)hi;
        *(uint2*)(sm + SM_XLO + off) = *(uint2*)lo;
    }
    #pragma unroll
    for (int i = 0; i < 4; i++) {
        int idx = tid + 256 * i;
        int row = idx >> 4, g = idx & 15;
        float f[4] = {wv[i].x, wv[i].y, wv[i].z, wv[i].w};
        __nv_bfloat16 hi[4], lo[4];
        #pragma unroll
        for (int j = 0; j < 4; j++) {
            hi[j] = __float2bfloat16(f[j]);
            lo[j] = __float2bfloat16(f[j] - __bfloat162float(hi[j]));
        }
        int off = row * ROWB + g * 8;
        *(uint2*)(sm + SM_WHI + off) = *(uint2*)hi;
        *(uint2*)(sm + SM_WLO + off) = *(uint2*)lo;
    }
}

__global__ __launch_bounds__(256) void k_gemm_mma(const float* __restrict__ x,
                                                  const float* __restrict__ Wp) {
    extern __shared__ char sm[];
    const int tid = threadIdx.x;
    const int w   = tid >> 5;
    const int lane = tid & 31;
    const int nodeBase = blockIdx.x * 128;

    float acc[8][4];
    #pragma unroll
    for (int nt = 0; nt < 8; nt++)
        #pragma unroll
        for (int j = 0; j < 4; j++) acc[nt][j] = 0.f;

    float4 xv[8], wv[4];
    load_chunk_regs(x, Wp, nodeBase, 0, tid, xv, wv);
    store_chunk_smem(sm, tid, xv, wv);
    __syncthreads();

    for (int c = 0; c < 4; c++) {
        if (c < 3) load_chunk_regs(x, Wp, nodeBase, (c + 1) * 64, tid, xv, wv);

        #pragma unroll
        for (int ks = 0; ks < 4; ks++) {
            const int kb = ks * 32 + (lane & 3) * 4;
            const int ar = (w * 16 + (lane >> 2)) * ROWB;
            uint32_t ah[4], al[4];
            ah[0] = lds_u32(sm + SM_XHI, ar + kb);
            ah[1] = lds_u32(sm + SM_XHI, ar + 8 * ROWB + kb);
            ah[2] = lds_u32(sm + SM_XHI, ar + kb + 16);
            ah[3] = lds_u32(sm + SM_XHI, ar + 8 * ROWB + kb + 16);
            al[0] = lds_u32(sm + SM_XLO, ar + kb);
            al[1] = lds_u32(sm + SM_XLO, ar + 8 * ROWB + kb);
            al[2] = lds_u32(sm + SM_XLO, ar + kb + 16);
            al[3] = lds_u32(sm + SM_XLO, ar + 8 * ROWB + kb + 16);

            #pragma unroll
            for (int nt = 0; nt < 8; nt++) {
                const int br = (nt * 8 + (lane >> 2)) * ROWB;
                uint32_t bh0 = lds_u32(sm + SM_WHI, br + kb);
                uint32_t bh1 = lds_u32(sm + SM_WHI, br + kb + 16);
                uint32_t bl0 = lds_u32(sm + SM_WLO, br + kb);
                uint32_t bl1 = lds_u32(sm + SM_WLO, br + kb + 16);
                mma_bf16(acc[nt], ah, bh0, bh1);
                mma_bf16(acc[nt], ah, bl0, bl1);
                mma_bf16(acc[nt], al, bh0, bh1);
            }
        }
        __syncthreads();
        if (c < 3) {
            store_chunk_smem(sm, tid, xv, wv);
            __syncthreads();
        }
    }

    // store as half2: col pair (nt*8 + (lane&3)*2, +1) -> index nt*4 + (lane&3)
    const int r0 = nodeBase + w * 16 + (lane >> 2);
    const int r1 = r0 + 8;
    #pragma unroll
    for (int nt = 0; nt < 8; nt++) {
        const int pj = nt * 4 + (lane & 3);
        if (r0 < N_NODES)
            g_yh[(size_t)r0 * 32 + pj] = __floats2half2_rn(acc[nt][0], acc[nt][1]);
        if (r1 < N_NODES)
            g_yh[(size_t)r1 * 32 + pj] = __floats2half2_rn(acc[nt][2], acc[nt][3]);
    }
}

// ---------------------------------------------------------------------------
// Gather: one warp per node, half2 rows (128B/neighbor = 1 sector per warp).
// acc = dinv[n]*y[n] + sum_r dinv[r]*y[r]; epilogue fused.
// ---------------------------------------------------------------------------
__global__ __launch_bounds__(256) void k_gather(const float* __restrict__ bias,
                                                const float* __restrict__ gamma,
                                                const float* __restrict__ beta,
                                                const float* __restrict__ mean,
                                                const float* __restrict__ var,
                                                float* __restrict__ out) {
    const int warp = (blockIdx.x * blockDim.x + threadIdx.x) >> 5;
    const int lane = threadIdx.x & 31;
    if (warp >= N_NODES) return;
    const int node = warp;
    const int c0 = lane * 2;

    const int s = g_off[node];
    const int e = s + g_deg[node];
    const float di = g_dinv[node];

    float2 sv = __half22float2(g_yh[(size_t)node * 32 + lane]);
    float2 acc = make_float2(sv.x * di, sv.y * di);   // self-loop term

    for (int base = s; base < e; base += 32) {
        int r = 0;
        float dr = 0.f;
        if (base + lane < e) {
            r = g_adj[base + lane];
            dr = g_dinv[r];
        }
        const int cnt = min(32, e - base);
        int j = 0;
        for (; j + 4 <= cnt; j += 4) {
            int r0 = __shfl_sync(0xffffffffu, r, j);
            int r1 = __shfl_sync(0xffffffffu, r, j + 1);
            int r2 = __shfl_sync(0xffffffffu, r, j + 2);
            int r3 = __shfl_sync(0xffffffffu, r, j + 3);
            float d0 = __shfl_sync(0xffffffffu, dr, j);
            float d1 = __shfl_sync(0xffffffffu, dr, j + 1);
            float d2 = __shfl_sync(0xffffffffu, dr, j + 2);
            float d3 = __shfl_sync(0xffffffffu, dr, j + 3);
            float2 v0 = __half22float2(g_yh[(size_t)r0 * 32 + lane]);
            float2 v1 = __half22float2(g_yh[(size_t)r1 * 32 + lane]);
            float2 v2 = __half22float2(g_yh[(size_t)r2 * 32 + lane]);
            float2 v3 = __half22float2(g_yh[(size_t)r3 * 32 + lane]);
            acc.x += d0 * v0.x + d1 * v1.x + d2 * v2.x + d3 * v3.x;
            acc.y += d0 * v0.y + d1 * v1.y + d2 * v2.y + d3 * v3.y;
        }
        for (; j < cnt; j++) {
            int rr = __shfl_sync(0xffffffffu, r, j);
            float dd = __shfl_sync(0xffffffffu, dr, j);
            float2 v = __half22float2(g_yh[(size_t)rr * 32 + lane]);
            acc.x += dd * v.x;
            acc.y += dd * v.y;
        }
    }

    float sc0 = rsqrtf(var[c0] + BN_EPS) * gamma[c0];
    float sc1 = rsqrtf(var[c0 + 1] + BN_EPS) * gamma[c0 + 1];
    float2 o;
    o.x = fmaxf((acc.x * di + bias[c0]     - mean[c0])     * sc0 + beta[c0],     0.f);
    o.y = fmaxf((acc.y * di + bias[c0 + 1] - mean[c0 + 1]) * sc1 + beta[c0 + 1], 0.f);
    *(float2*)&out[(size_t)node * D_OUT + c0] = o;
}

// ---------------------------------------------------------------------------
extern "C" void kernel_launch(void* const* d_in, const int* in_sizes, int n_in,
                              void* d_out, int out_size) {
    const float* x     = (const float*)d_in[0];
    const int*   ei    = (const int*)  d_in[1];
    const float* W     = (const float*)d_in[2];
    const float* bias  = (const float*)d_in[3];
    const float* gamma = (const float*)d_in[4];
    const float* beta  = (const float*)d_in[5];
    const float* mean  = (const float*)d_in[6];
    const float* var   = (const float*)d_in[7];
    float* out = (float*)d_out;

    const int* rows = ei;            // edge_index[0] = source
    const int* cols = ei + N_EDGES;  // edge_index[1] = target

    static cudaStream_t s2 = nullptr;
    static cudaEvent_t evFork = nullptr, evJoin = nullptr;
    if (!s2) {
        cudaStreamCreateWithFlags(&s2, cudaStreamNonBlocking);
        cudaEventCreateWithFlags(&evFork, cudaEventDisableTiming);
        cudaEventCreateWithFlags(&evJoin, cudaEventDisableTiming);
        cudaFuncSetAttribute(k_gemm_mma, cudaFuncAttributeMaxDynamicSharedMemorySize, SM_TOTAL);
    }

    // fork: CSR build on s2, GEMM on the capture (default) stream
    cudaEventRecord(evFork, 0);
    cudaStreamWaitEvent(s2, evFork, 0);

    k_zero   <<<(N_NODES + 255) / 256, 256, 0, s2>>>();
    k_count  <<<(N_EDGES + 255) / 256, 256, 0, s2>>>(cols);
    k_offsets<<<(N_NODES + 255) / 256, 256, 0, s2>>>();
    k_fill   <<<(N_EDGES + 255) / 256, 256, 0, s2>>>(rows, cols);

    k_gemm_mma<<<(N_NODES + 127) / 128, 256, SM_TOTAL>>>(x, W);

    // join
    cudaEventRecord(evJoin, s2);
    cudaStreamWaitEvent(0, evJoin, 0);

    k_gather<<<(N_NODES * 32 + 255) / 256, 256>>>(bias, gamma, beta, mean, var, out);
}